// round 4
// baseline (speedup 1.0000x reference)
#include <cuda_runtime.h>
#include <cuda_bf16.h>
#include <math.h>

// Problem constants
#define NN     8192
#define IN_F   256
#define OUT_F  128
#define ALPHA  0.2f

#define ADJ_WORDS_PER_ROW (NN / 32)   // 256
#define MAXDEG 128

// Scratch (device globals; no allocation)
__device__ unsigned g_adj[NN * ADJ_WORDS_PER_ROW];   // 8 MB bitmask (dedup + fallback)
__device__ int      g_deg[NN];                       // deduped degree
__device__ int      g_nbr[NN * MAXDEG];              // CSR-ish neighbor lists (4 MB)
__device__ float    g_Wh[NN * OUT_F];                // 4 MB
__device__ float    g_s1[NN];
__device__ float    g_s2[NN];

// ---------------------------------------------------------------------------
// Kernel 1: zero adjacency bitmask + degree array
// ---------------------------------------------------------------------------
__global__ __launch_bounds__(256) void zero_adj_kernel() {
    int idx = blockIdx.x * blockDim.x + threadIdx.x;      // uint4 index
    const int total = (NN * ADJ_WORDS_PER_ROW) / 4;       // 524288
    if (idx < total) {
        ((uint4*)g_adj)[idx] = make_uint4(0u, 0u, 0u, 0u);
    }
    if (idx < NN) g_deg[idx] = 0;
}

// ---------------------------------------------------------------------------
// Kernel 2: scatter edges; bitmask atomicOr dedups, unique edges appended to
// the per-row neighbor list. edge_index is int32.
// ---------------------------------------------------------------------------
__global__ __launch_bounds__(256) void scatter_kernel(const int* __restrict__ edge_index,
                                                      int E) {
    int k = blockIdx.x * blockDim.x + threadIdx.x;
    if (k < E) {
        int src = edge_index[k]     & (NN - 1);
        int dst = edge_index[E + k] & (NN - 1);
        unsigned bit = 1u << (dst & 31);
        unsigned old = atomicOr(&g_adj[src * ADJ_WORDS_PER_ROW + (dst >> 5)], bit);
        if (!(old & bit)) {
            int pos = atomicAdd(&g_deg[src], 1);
            if (pos < MAXDEG) g_nbr[src * MAXDEG + pos] = dst;
        }
    }
}

// ---------------------------------------------------------------------------
// Kernel 3: Wh = h @ W^T + b_lin (fused s1/s2 epilogue), register prefetch
// ---------------------------------------------------------------------------
__global__ __launch_bounds__(256) void gemm_s_kernel(const float* __restrict__ h,
                                                     const float* __restrict__ W,
                                                     const float* __restrict__ b_lin,
                                                     const float* __restrict__ a) {
    const int BM = 64, BK = 32;
    __shared__ float hs[BK][BM];       // hs[k][m]
    __shared__ float ws[BK][OUT_F];    // ws[k][n]

    int row0 = blockIdx.x * BM;
    int tid  = threadIdx.x;
    int tr   = tid >> 5;   // warp id 0..7
    int tc   = tid & 31;   // lane

    // per-thread load coordinates
    int hm0 = (tid + 0)   >> 3, hk0 = (tid + 0)   & 7;
    int hm1 = (tid + 256) >> 3, hk1 = (tid + 256) & 7;
    int wn[4], wk[4];
#pragma unroll
    for (int l = 0; l < 4; l++) { wn[l] = (tid + 256 * l) >> 3; wk[l] = (tid + 256 * l) & 7; }

    float acc[8][4];
#pragma unroll
    for (int i = 0; i < 8; i++)
#pragma unroll
        for (int j = 0; j < 4; j++) acc[i][j] = 0.0f;

    // prefetch tile 0
    float4 ph0 = *(const float4*)&h[(row0 + hm0) * IN_F + hk0 * 4];
    float4 ph1 = *(const float4*)&h[(row0 + hm1) * IN_F + hk1 * 4];
    float4 pw[4];
#pragma unroll
    for (int l = 0; l < 4; l++) pw[l] = *(const float4*)&W[wn[l] * IN_F + wk[l] * 4];

    for (int k0 = 0; k0 < IN_F; k0 += BK) {
        // commit prefetched tile to smem
        hs[hk0 * 4 + 0][hm0] = ph0.x; hs[hk0 * 4 + 1][hm0] = ph0.y;
        hs[hk0 * 4 + 2][hm0] = ph0.z; hs[hk0 * 4 + 3][hm0] = ph0.w;
        hs[hk1 * 4 + 0][hm1] = ph1.x; hs[hk1 * 4 + 1][hm1] = ph1.y;
        hs[hk1 * 4 + 2][hm1] = ph1.z; hs[hk1 * 4 + 3][hm1] = ph1.w;
#pragma unroll
        for (int l = 0; l < 4; l++) {
            ws[wk[l] * 4 + 0][wn[l]] = pw[l].x;
            ws[wk[l] * 4 + 1][wn[l]] = pw[l].y;
            ws[wk[l] * 4 + 2][wn[l]] = pw[l].z;
            ws[wk[l] * 4 + 3][wn[l]] = pw[l].w;
        }
        __syncthreads();

        // issue next tile's loads to overlap with compute
        if (k0 + BK < IN_F) {
            int kn = k0 + BK;
            ph0 = *(const float4*)&h[(row0 + hm0) * IN_F + kn + hk0 * 4];
            ph1 = *(const float4*)&h[(row0 + hm1) * IN_F + kn + hk1 * 4];
#pragma unroll
            for (int l = 0; l < 4; l++) pw[l] = *(const float4*)&W[wn[l] * IN_F + kn + wk[l] * 4];
        }

#pragma unroll
        for (int k = 0; k < BK; k++) {
            float4 ha = *(const float4*)&hs[k][tr * 8];
            float4 hb = *(const float4*)&hs[k][tr * 8 + 4];
            float4 wb = *(const float4*)&ws[k][tc * 4];
            float ra[8] = {ha.x, ha.y, ha.z, ha.w, hb.x, hb.y, hb.z, hb.w};
            float rb[4] = {wb.x, wb.y, wb.z, wb.w};
#pragma unroll
            for (int i = 0; i < 8; i++)
#pragma unroll
                for (int j = 0; j < 4; j++)
                    acc[i][j] = fmaf(ra[i], rb[j], acc[i][j]);
        }
        __syncthreads();
    }

    // epilogue: bias, store Wh, fused s1/s2
    int col = tc * 4;
    float4 blv = *(const float4*)&b_lin[col];
    float4 a1v = *(const float4*)&a[col];
    float4 a2v = *(const float4*)&a[OUT_F + col];
    float bl[4]  = {blv.x, blv.y, blv.z, blv.w};
    float a1r[4] = {a1v.x, a1v.y, a1v.z, a1v.w};
    float a2r[4] = {a2v.x, a2v.y, a2v.z, a2v.w};

#pragma unroll
    for (int i = 0; i < 8; i++) {
        int row = row0 + tr * 8 + i;
        float v0 = acc[i][0] + bl[0];
        float v1 = acc[i][1] + bl[1];
        float v2 = acc[i][2] + bl[2];
        float v3 = acc[i][3] + bl[3];
        *(float4*)&g_Wh[row * OUT_F + col] = make_float4(v0, v1, v2, v3);
        float p1 = v0 * a1r[0] + v1 * a1r[1] + v2 * a1r[2] + v3 * a1r[3];
        float p2 = v0 * a2r[0] + v1 * a2r[1] + v2 * a2r[2] + v3 * a2r[3];
#pragma unroll
        for (int o = 16; o > 0; o >>= 1) {
            p1 += __shfl_xor_sync(0xffffffffu, p1, o);
            p2 += __shfl_xor_sync(0xffffffffu, p2, o);
        }
        if (tc == 0) {
            g_s1[row] = p1;
            g_s2[row] = p2;
        }
    }
}

// ---------------------------------------------------------------------------
// Block reductions (128 threads)
// ---------------------------------------------------------------------------
__device__ __forceinline__ float blk_reduce_max(float v, float* buf) {
#pragma unroll
    for (int o = 16; o > 0; o >>= 1)
        v = fmaxf(v, __shfl_xor_sync(0xffffffffu, v, o));
    int w = threadIdx.x >> 5;
    if ((threadIdx.x & 31) == 0) buf[w] = v;
    __syncthreads();
    float r = fmaxf(fmaxf(buf[0], buf[1]), fmaxf(buf[2], buf[3]));
    __syncthreads();
    return r;
}

__device__ __forceinline__ float blk_reduce_sum(float v, float* buf) {
#pragma unroll
    for (int o = 16; o > 0; o >>= 1)
        v += __shfl_xor_sync(0xffffffffu, v, o);
    int w = threadIdx.x >> 5;
    if ((threadIdx.x & 31) == 0) buf[w] = v;
    __syncthreads();
    float r = buf[0] + buf[1] + buf[2] + buf[3];
    __syncthreads();
    return r;
}

// ---------------------------------------------------------------------------
// Kernel 4: per-row softmax + aggregation + ELU using CSR lists.
// Fast path: deg <= MAXDEG (always, in practice). Fallback: bitmask scan.
// ---------------------------------------------------------------------------
__global__ __launch_bounds__(128) void attn_kernel(const float* __restrict__ b_att_p,
                                                   float* __restrict__ out) {
    __shared__ int   sjn[MAXDEG];
    __shared__ float se[MAXDEG];
    __shared__ float swt[MAXDEG];
    __shared__ float rbuf[4];
    __shared__ int   s_cnt;

    int i   = blockIdx.x;
    int tid = threadIdx.x;
    float batt = *b_att_p;
    float s1i  = g_s1[i];
    int deg = g_deg[i];

    if (deg == 0) {
        // uniform softmax over all N (never hit for random graphs; exact anyway)
        float accm = 0.0f;
        for (int j = 0; j < NN; j++) accm += g_Wh[j * OUT_F + tid];
        float v = accm * (1.0f / (float)NN);
        out[i * OUT_F + tid] = (v > 0.0f) ? v : expm1f(v);
        return;
    }

    if (deg <= MAXDEG) {
        // --- fast path: neighbor list in smem ---
        const int* nbr = &g_nbr[i * MAXDEG];
        float lmax = -INFINITY;
        for (int k = tid; k < deg; k += 128) {
            int j = nbr[k];
            float t = s1i + g_s2[j] + batt;
            float e = (t > 0.0f) ? t : ALPHA * t;
            sjn[k] = j;
            se[k]  = e;
            lmax = fmaxf(lmax, e);
        }
        float m = blk_reduce_max(lmax, rbuf);   // barrier also publishes sjn/se

        float ls = 0.0f;
        for (int k = tid; k < deg; k += 128) {
            float w = expf(se[k] - m);
            swt[k] = w;
            ls += w;
        }
        float sumw = blk_reduce_sum(ls, rbuf);  // barrier also publishes swt

        // aggregation: thread tid owns feature tid; coalesced 512B row gathers
        float acc = 0.0f;
        int k = 0;
        for (; k + 4 <= deg; k += 4) {
            int   j0 = sjn[k],     j1 = sjn[k + 1], j2 = sjn[k + 2], j3 = sjn[k + 3];
            float w0 = swt[k],     w1 = swt[k + 1], w2 = swt[k + 2], w3 = swt[k + 3];
            float v0 = g_Wh[j0 * OUT_F + tid];
            float v1 = g_Wh[j1 * OUT_F + tid];
            float v2 = g_Wh[j2 * OUT_F + tid];
            float v3 = g_Wh[j3 * OUT_F + tid];
            acc = fmaf(w0, v0, acc);
            acc = fmaf(w1, v1, acc);
            acc = fmaf(w2, v2, acc);
            acc = fmaf(w3, v3, acc);
        }
        for (; k < deg; k++)
            acc = fmaf(swt[k], g_Wh[sjn[k] * OUT_F + tid], acc);

        float v = acc / sumw;
        out[i * OUT_F + tid] = (v > 0.0f) ? v : expm1f(v);
        return;
    }

    // --- fallback: bitmask scan (deg > MAXDEG; correctness safety net) ---
    uint2 wv = *(const uint2*)&g_adj[i * ADJ_WORDS_PER_ROW + tid * 2];
    unsigned long long rem = (unsigned long long)wv.x | ((unsigned long long)wv.y << 32);
    int base = tid * 64;

    float lmax = -INFINITY;
    {
        unsigned long long m0 = rem;
        while (m0) {
            int b = __ffsll(m0) - 1;
            m0 &= m0 - 1;
            int j = base + b;
            float t = s1i + g_s2[j] + batt;
            float e = (t > 0.0f) ? t : ALPHA * t;
            lmax = fmaxf(lmax, e);
        }
    }
    float m = blk_reduce_max(lmax, rbuf);

    float acc = 0.0f, sumw = 0.0f;
    for (;;) {
        if (tid == 0) s_cnt = 0;
        __syncthreads();
        while (rem) {
            int b   = __ffsll(rem) - 1;
            int pos = atomicAdd(&s_cnt, 1);
            if (pos >= MAXDEG) break;
            rem &= rem - 1;
            int j = base + b;
            float t = s1i + g_s2[j] + batt;
            float e = (t > 0.0f) ? t : ALPHA * t;
            sjn[pos] = j;
            swt[pos] = expf(e - m);
        }
        __syncthreads();
        int cnt = min(s_cnt, MAXDEG);

        float ls = 0.0f;
        for (int k = tid; k < cnt; k += 128) ls += swt[k];
        sumw += blk_reduce_sum(ls, rbuf);

        for (int k = 0; k < cnt; k++)
            acc = fmaf(swt[k], g_Wh[sjn[k] * OUT_F + tid], acc);

        if (!__syncthreads_or(rem != 0ull)) break;
    }

    float v = acc / sumw;
    out[i * OUT_F + tid] = (v > 0.0f) ? v : expm1f(v);
}

// ---------------------------------------------------------------------------
// Launch
// Inputs: 0:h [N,256] f32, 1:edge_index [2,E] i32, 2:W [128,256] f32,
//         3:b_lin [128] f32, 4:a [1,256] f32, 5:b_att [1] f32
// ---------------------------------------------------------------------------
extern "C" void kernel_launch(void* const* d_in, const int* in_sizes, int n_in,
                              void* d_out, int out_size) {
    const float* h     = (const float*)d_in[0];
    const int*   ei    = (const int*)d_in[1];
    const float* W     = (const float*)d_in[2];
    const float* b_lin = (const float*)d_in[3];
    const float* a     = (const float*)d_in[4];
    const float* b_att = (const float*)d_in[5];
    float* out = (float*)d_out;

    int E = in_sizes[1] / 2;

    {
        int total = (NN * ADJ_WORDS_PER_ROW) / 4;
        zero_adj_kernel<<<(total + 255) / 256, 256>>>();
    }
    scatter_kernel<<<(E + 255) / 256, 256>>>(ei, E);
    gemm_s_kernel<<<NN / 64, 256>>>(h, W, b_lin, a);
    attn_kernel<<<NN, 128>>>(b_att, out);
}